// round 11
// baseline (speedup 1.0000x reference)
#include <cuda_runtime.h>
#include <cuda_fp16.h>
#include <cstdint>
#include <cstddef>

// Problem constants
#define TT   512
#define BB   32
#define HH   1024
#define G4H  4096
#define NBLK 128           // persistent recurrent grid (co-resident)

// ---------------- scratch ----------------
__device__ float g_xg[(size_t)TT * BB * G4H];     // input projection (fp32 [t][b][4H])
__device__ uint4 g_xa[2097152];                   // packed-A fp16 X (layer 0), 32MB
__device__ uint4 g_x1[2097152];                   // packed-A fp16 layer-0 output, 32MB
__device__ uint4 g_wb[1048576];                   // packed-B fp16 weights (16MB), per layer
__device__ uint4 g_hb[2][4096];                   // packed-A fp16 hidden state, ping-pong (2x64KB)
__device__ unsigned int          g_cnt1[8 * 32];
__device__ unsigned int          g_cnt2;
__device__ volatile unsigned int g_gen;

__device__ __forceinline__ float sigm(float x) {
    return 1.0f / (1.0f + expf(-x));
}

// pack two floats into one fp16x2 register (lo = first arg)
__device__ __forceinline__ uint32_t h2pack(float lo, float hi) {
    __half2 h = __floats2half2_rn(lo, hi);
    return *(uint32_t*)&h;
}

// fp16 tensor-core mma, fp32 accumulate
__device__ __forceinline__ void mma16816(float c[4],
    uint32_t a0, uint32_t a1, uint32_t a2, uint32_t a3,
    uint32_t b0, uint32_t b1)
{
    asm volatile(
        "mma.sync.aligned.m16n8k16.row.col.f32.f16.f16.f32 "
        "{%0,%1,%2,%3}, {%4,%5,%6,%7}, {%8,%9}, {%0,%1,%2,%3};"
        : "+f"(c[0]), "+f"(c[1]), "+f"(c[2]), "+f"(c[3])
        : "r"(a0), "r"(a1), "r"(a2), "r"(a3), "r"(b0), "r"(b1));
}

// Two-level grid barrier: 8 groups x 16 blocks. All NBLK blocks co-resident.
// (Exact R9 version — known good.)
__device__ __forceinline__ void grid_barrier() {
    __syncthreads();
    if (threadIdx.x == 0) {
        __threadfence();
        unsigned int g = g_gen;
        unsigned int grp = blockIdx.x & 7u;
        if (atomicAdd(&g_cnt1[grp * 32], 1u) == 15u) {
            if (atomicAdd(&g_cnt2, 1u) == 7u) {
#pragma unroll
                for (int i = 0; i < 8; ++i) g_cnt1[i * 32] = 0u;
                g_cnt2 = 0u;
                __threadfence();
                g_gen = g + 1u;
            }
        }
        while (g_gen == g) { }
        __threadfence();
    }
    __syncthreads();
}

// =====================================================================
// Packing converters (fp32 -> fp16 mma fragments)
// A slot s = ((mb*64+kt)*8+rg)*32+lane : uint4 {a0,a1,a2,a3} for
//   rows mb*128+rg*16+{g,g+8}, k = kt*16+{2tig,2tig+1,8+2tig,9+2tig}
// =====================================================================
__global__ void __launch_bounds__(256) conv_pack_a(
    const float* __restrict__ X, uint4* __restrict__ Ap)
{
    int s = blockIdx.x * 256 + threadIdx.x;
    int lane = s & 31, rg = (s >> 5) & 7, kt = (s >> 8) & 63, mb = s >> 14;
    int g = lane >> 2, tig = lane & 3;
    int r0 = mb * 128 + rg * 16 + g;
    int k0 = kt * 16 + 2 * tig;
    const float* p0 = X + (size_t)r0 * HH;
    const float* p1 = X + (size_t)(r0 + 8) * HH;
    uint4 v;
    v.x = h2pack(p0[k0],     p0[k0 + 1]);
    v.y = h2pack(p1[k0],     p1[k0 + 1]);
    v.z = h2pack(p0[k0 + 8], p0[k0 + 9]);
    v.w = h2pack(p1[k0 + 8], p1[k0 + 9]);
    Ap[s] = v;
}

// B slot (uint2) s = ((nb*64+kt)*16+cg)*32+lane :
//   n = nb*128+cg*8+g, b0 = {W[n][kt*16+2tig], +1}, b1 = {+8, +9}
__global__ void __launch_bounds__(256) conv_pack_b(
    const float* __restrict__ W, uint2* __restrict__ Bp)
{
    int s = blockIdx.x * 256 + threadIdx.x;
    int lane = s & 31, cg = (s >> 5) & 15, kt = (s >> 9) & 63, nb = s >> 15;
    int g = lane >> 2, tig = lane & 3;
    int n  = nb * 128 + cg * 8 + g;
    int k0 = kt * 16 + 2 * tig;
    const float* p = W + (size_t)n * HH;
    Bp[s] = make_uint2(h2pack(p[k0], p[k0 + 1]), h2pack(p[k0 + 8], p[k0 + 9]));
}

// =====================================================================
// Input projection GEMM, fp16 tensor cores, cp.async 4-deep smem pipeline,
// 2 blocks/SM to fill sync bubbles. (THE one change vs R9.)
//   Y[m][n] = sum_k X[m][k]*W[n][k] + bi[n],  M=16384, N=4096, K=1024
//   512 threads, 16 warps (wm 0..3 x wn 0..3), warp tile 32x32.
//   smem: 4 stages x (A 4KB + B 4KB) = 32KB dynamic.
// =====================================================================
#define STG 4
#define GEMM_SMEM (STG * 512 * 16)

__global__ void __launch_bounds__(512, 2) gemm_h(
    const uint4* __restrict__ Ap, const uint4* __restrict__ Bp4,
    const float* __restrict__ bi, float* __restrict__ Y)
{
    extern __shared__ uint4 sm[];   // [stage*512 + (A:0..255 | B:256..511)]

    const int tid  = threadIdx.x;
    const int warp = tid >> 5;
    const int lane = tid & 31;
    const int wm   = warp >> 2;
    const int wn   = warp & 3;
    const int nb   = blockIdx.x;
    const int mb   = blockIdx.y;

    const uint4* Ab4 = Ap  + (size_t)mb * 16384;
    const uint4* Bb4 = Bp4 + (size_t)nb * 16384;

    // per-thread cp.async source/dest partition
    const int j = tid & 255;
    const bool isA = tid < 256;
    const uint4* srcBase = isA ? Ab4 : Bb4;
    const int dstOff = (isA ? 0 : 256) + j;

    float C[2][4][4];
#pragma unroll
    for (int a = 0; a < 2; ++a)
#pragma unroll
        for (int b = 0; b < 4; ++b)
#pragma unroll
            for (int c = 0; c < 4; ++c) C[a][b][c] = 0.0f;

#define ISSUE(kt)                                                                   \
    {                                                                               \
        uint32_t d = (uint32_t)__cvta_generic_to_shared(                            \
            &sm[((kt) & (STG - 1)) * 512 + dstOff]);                                \
        const uint4* s_ = srcBase + (size_t)(kt) * 256 + j;                         \
        asm volatile("cp.async.cg.shared.global [%0], [%1], 16;\n" :: "r"(d), "l"(s_)); \
        asm volatile("cp.async.commit_group;\n");                                   \
    }

#pragma unroll
    for (int kt = 0; kt < STG - 1; ++kt) ISSUE(kt);

#pragma unroll 1
    for (int kt = 0; kt < 64; ++kt) {
        asm volatile("cp.async.wait_group %0;\n" :: "n"(STG - 2) : "memory");
        __syncthreads();
        if (kt + STG - 1 < 64) ISSUE(kt + STG - 1);

        const int st = kt & (STG - 1);
        uint4 au[2];
#pragma unroll
        for (int mt = 0; mt < 2; ++mt)
            au[mt] = sm[st * 512 + (wm * 2 + mt) * 32 + lane];
        const uint2* b2 = (const uint2*)(sm + st * 512 + 256);
        uint2 bu[4];
#pragma unroll
        for (int cg = 0; cg < 4; ++cg)
            bu[cg] = b2[(wn * 4 + cg) * 32 + lane];
#pragma unroll
        for (int mt = 0; mt < 2; ++mt)
#pragma unroll
            for (int cg = 0; cg < 4; ++cg)
                mma16816(C[mt][cg], au[mt].x, au[mt].y, au[mt].z, au[mt].w,
                         bu[cg].x, bu[cg].y);
    }
#undef ISSUE

    const int g = lane >> 2, tig = lane & 3;
#pragma unroll
    for (int mt = 0; mt < 2; ++mt) {
#pragma unroll
        for (int cg = 0; cg < 4; ++cg) {
            int row = mb * 128 + wm * 32 + mt * 16 + g;
            int col = nb * 128 + wn * 32 + cg * 8 + 2 * tig;
            float b0 = bi[col], b1 = bi[col + 1];
            *(float2*)(Y + (size_t)row * G4H + col) =
                make_float2(C[mt][cg][0] + b0, C[mt][cg][1] + b1);
            *(float2*)(Y + (size_t)(row + 8) * G4H + col) =
                make_float2(C[mt][cg][2] + b0, C[mt][cg][3] + b1);
        }
    }
}

// =====================================================================
// Persistent recurrent kernel — EXACT R9 version (known good, 2.449us/step).
// 256 threads / 8 warps, fp16 operands, R register-resident,
// 4-deep pipelined h fragment loads, scalar partial stores.
// =====================================================================
__global__ void __launch_bounds__(256, 1) recurrent_h(
    const float* __restrict__ xg,   // [T][B][4H]
    const float* __restrict__ R,    // [4H][H]
    const float* __restrict__ bh,   // [4H]
    const float* __restrict__ h0,   // [B][H]
    const float* __restrict__ c0,   // [B][H]
    float* __restrict__ outp,
    float* __restrict__ hT,         // [B][H]
    float* __restrict__ cT,         // [B][H]
    int mode)
{
    __shared__ float part[32 * 296];   // part[b][w][j] : b*296 + w*37 + j

    const int tid  = threadIdx.x;
    const int w    = tid >> 5;
    const int lane = tid & 31;
    const int g    = lane >> 2;
    const int tig  = lane & 3;
    const int n0   = blockIdx.x * 8;

    // ---- Preload R fp16 B-fragments into registers ----
    uint32_t Br[4][8][2];
#pragma unroll
    for (int cg = 0; cg < 4; ++cg) {
        const float* rp = R + (size_t)(cg * HH + n0 + g) * HH + w * 128 + 2 * tig;
#pragma unroll
        for (int ks = 0; ks < 8; ++ks) {
            const float* q = rp + ks * 16;
            Br[cg][ks][0] = h2pack(__ldg(q),     __ldg(q + 1));
            Br[cg][ks][1] = h2pack(__ldg(q + 8), __ldg(q + 9));
        }
    }

    // ---- Convert h0 into packed fp16 HB[0] (32 slots per block) ----
    if (tid < 32) {
        int slot = blockIdx.x * 32 + tid;            // 0..4095
        int ls = slot & 31, mts = (slot >> 5) & 1, kt = slot >> 6;
        int gs = ls >> 2, ts = ls & 3;
        int r0 = mts * 16 + gs;
        int k0 = kt * 16 + 2 * ts;
        const float* p0 = h0 + (size_t)r0 * HH;
        const float* p1 = h0 + (size_t)(r0 + 8) * HH;
        uint4 v;
        v.x = h2pack(p0[k0],     p0[k0 + 1]);
        v.y = h2pack(p1[k0],     p1[k0 + 1]);
        v.z = h2pack(p0[k0 + 8], p0[k0 + 9]);
        v.w = h2pack(p1[k0 + 8], p1[k0 + 9]);
        g_hb[0][slot] = v;
    }

    // ---- update-phase constants ----
    const int ub = tid >> 3;   // b 0..31
    const int un = tid & 7;    // n-offset 0..7
    const int hid = n0 + un;
    float bhv[4];
#pragma unroll
    for (int gg = 0; gg < 4; ++gg) bhv[gg] = bh[gg * HH + hid];
    float creg = c0[ub * HH + hid];

    // fp16 h write address for (ub, hid) inside HB slot
    const int hw_mt = ub >> 4, hw_row16 = ub & 15;
    const int hw_g = hw_row16 & 7, hw_rh = hw_row16 >> 3;
    const int hw_kt = hid >> 4, hw_k15 = hid & 15;
    const int hw_kh = hw_k15 >> 3, hw_tig = (hw_k15 & 7) >> 1, hw_hs = hw_k15 & 1;
    const int hb_slot = (hw_kt * 2 + hw_mt) * 32 + hw_g * 4 + hw_tig;
    const int hb_half = (hw_kh * 2 + hw_rh) * 2 + hw_hs;   // half index within uint4
    __half* hb_w[2] = { (__half*)&g_hb[0][hb_slot] + hb_half,
                        (__half*)&g_hb[1][hb_slot] + hb_half };

    grid_barrier();   // HB[0] ready everywhere

    for (int t = 0; t < TT; ++t) {
        const uint4* hp = g_hb[t & 1];

        // prefetch xg for update phase
        const float* xgt = xg + ((size_t)t * BB + ub) * G4H + hid;
        float xv[4];
#pragma unroll
        for (int gg = 0; gg < 4; ++gg) xv[gg] = __ldg(xgt + gg * HH);

        float Cr[2][4][4];
#pragma unroll
        for (int a = 0; a < 2; ++a)
#pragma unroll
            for (int b = 0; b < 4; ++b)
#pragma unroll
                for (int c = 0; c < 4; ++c) Cr[a][b][c] = 0.0f;

        // 4-deep pipelined h fragment loads (LDG.128, L2-coherent)
        uint4 Ab[4][2];
#pragma unroll
        for (int p = 0; p < 4; ++p)
#pragma unroll
            for (int mt = 0; mt < 2; ++mt)
                Ab[p][mt] = __ldcg(&hp[((w * 8 + p) * 2 + mt) * 32 + lane]);

#pragma unroll
        for (int ks = 0; ks < 8; ++ks) {
            const int pb = ks & 3;
            uint4 a0 = Ab[pb][0];
            uint4 a1 = Ab[pb][1];
            if (ks + 4 < 8) {
#pragma unroll
                for (int mt = 0; mt < 2; ++mt)
                    Ab[pb][mt] = __ldcg(&hp[((w * 8 + (ks + 4)) * 2 + mt) * 32 + lane]);
            }
#pragma unroll
            for (int cg = 0; cg < 4; ++cg) {
                mma16816(Cr[0][cg], a0.x, a0.y, a0.z, a0.w, Br[cg][ks][0], Br[cg][ks][1]);
                mma16816(Cr[1][cg], a1.x, a1.y, a1.z, a1.w, Br[cg][ks][0], Br[cg][ks][1]);
            }
        }

        // store partials to smem (SCALAR stores: stride 37 is odd -> no float2)
#pragma unroll
        for (int mt = 0; mt < 2; ++mt) {
#pragma unroll
            for (int cg = 0; cg < 4; ++cg) {
                int b = mt * 16 + g;
                int jj = cg * 8 + 2 * tig;
                part[b * 296 + w * 37 + jj]           = Cr[mt][cg][0];
                part[b * 296 + w * 37 + jj + 1]       = Cr[mt][cg][1];
                part[(b + 8) * 296 + w * 37 + jj]     = Cr[mt][cg][2];
                part[(b + 8) * 296 + w * 37 + jj + 1] = Cr[mt][cg][3];
            }
        }
        __syncthreads();

        // reduce over 8 warps + gate math. gates order: i, o, z, f
        float gate[4];
#pragma unroll
        for (int gg = 0; gg < 4; ++gg) {
            float s = xv[gg] + bhv[gg];
#pragma unroll
            for (int wi = 0; wi < 8; ++wi)
                s += part[ub * 296 + wi * 37 + gg * 8 + un];
            gate[gg] = sigm(s);
        }
        creg = creg * gate[3] + gate[2] - gate[0];   // c = c*f + z - i
        float hval = sigm(creg) - gate[1];           // h = sigm(c) - o

        if (mode == 0) {
            // packed-A fp16 layout for layer-1 gemm
            int m = t * BB + ub;
            int mb = m >> 7, r = m & 127;
            int rg_ = r >> 4, row16 = r & 15;
            int g_ = row16 & 7, rh_ = row16 >> 3;
            size_t slot = ((size_t)(mb * 64 + hw_kt) * 8 + rg_) * 32 + g_ * 4 + hw_tig;
            ((__half*)&((uint4*)outp)[slot])[(hw_kh * 2 + rh_) * 2 + hw_hs] =
                __float2half_rn(hval);
        } else {
            outp[((size_t)t * BB + ub) * HH + hid] = hval;
        }

        // fp16 HB store for next step
        *hb_w[(t + 1) & 1] = __float2half_rn(hval);

        if (t == TT - 1) {
            hT[ub * HH + hid] = hval;
            cT[ub * HH + hid] = creg;
        }

        grid_barrier();
    }
}

// ---------------- launch ----------------
extern "C" void kernel_launch(void* const* d_in, const int* in_sizes, int n_in,
                              void* d_out, int out_size)
{
    (void)in_sizes; (void)n_in; (void)out_size;
    const float* x   = (const float*)d_in[0];
    const float* h0  = (const float*)d_in[1];
    const float* c0  = (const float*)d_in[2];
    const float* W0  = (const float*)d_in[3];
    const float* R0  = (const float*)d_in[4];
    const float* bi0 = (const float*)d_in[5];
    const float* bh0 = (const float*)d_in[6];
    const float* W1  = (const float*)d_in[7];
    const float* R1  = (const float*)d_in[8];
    const float* bi1 = (const float*)d_in[9];
    const float* bh1 = (const float*)d_in[10];

    float* out = (float*)d_out;
    float* hT  = out + (size_t)TT * BB * HH;
    float* cT  = hT + (size_t)2 * BB * HH;

    float* xg = nullptr;  cudaGetSymbolAddress((void**)&xg, g_xg);
    uint4* xa = nullptr;  cudaGetSymbolAddress((void**)&xa, g_xa);
    uint4* x1 = nullptr;  cudaGetSymbolAddress((void**)&x1, g_x1);
    uint4* wb = nullptr;  cudaGetSymbolAddress((void**)&wb, g_wb);

    cudaFuncSetAttribute(gemm_h, cudaFuncAttributeMaxDynamicSharedMemorySize, GEMM_SMEM);

    dim3 ggrid(G4H / 128, (TT * BB) / 128);  // (32, 128)

    // Layer 0
    conv_pack_a<<<2097152 / 256, 256>>>(x, xa);
    conv_pack_b<<<1048576 / 256, 256>>>(W0, (uint2*)wb);
    gemm_h<<<ggrid, 512, GEMM_SMEM>>>(xa, wb, bi0, xg);
    recurrent_h<<<NBLK, 256>>>(xg, R0, bh0, h0, c0, (float*)x1, hT, cT, 0);
    // Layer 1
    conv_pack_b<<<1048576 / 256, 256>>>(W1, (uint2*)wb);
    gemm_h<<<ggrid, 512, GEMM_SMEM>>>(x1, wb, bi1, xg);
    recurrent_h<<<NBLK, 256>>>(xg, R1, bh1, h0 + BB * HH, c0 + BB * HH,
                               out, hT + BB * HH, cT + BB * HH, 1);
}

// round 12
// speedup vs baseline: 1.0833x; 1.0833x over previous
#include <cuda_runtime.h>
#include <cuda_fp16.h>
#include <cstdint>
#include <cstddef>

// Problem constants
#define TT   512
#define BB   32
#define HH   1024
#define G4H  4096
#define NBLK 128           // persistent recurrent grid (co-resident)

// ---------------- scratch ----------------
__device__ float g_xg[(size_t)TT * BB * G4H];     // input projection (fp32 [t][b][4H])
__device__ uint4 g_xa[2097152];                   // packed-A fp16 X (layer 0), 32MB
__device__ uint4 g_x1[2097152];                   // packed-A fp16 layer-0 output, 32MB
__device__ uint4 g_wb[1048576];                   // packed-B fp16 weights (16MB), per layer
__device__ uint4 g_hb[2][4096];                   // packed-A fp16 hidden state, ping-pong (2x64KB)
__device__ unsigned int          g_cnt;
__device__ volatile unsigned int g_gen;

__device__ __forceinline__ float sigm(float x) {
    return 1.0f / (1.0f + expf(-x));
}

// pack two floats into one fp16x2 register (lo = first arg)
__device__ __forceinline__ uint32_t h2pack(float lo, float hi) {
    __half2 h = __floats2half2_rn(lo, hi);
    return *(uint32_t*)&h;
}

// fp16 tensor-core mma, fp32 accumulate
__device__ __forceinline__ void mma16816(float c[4],
    uint32_t a0, uint32_t a1, uint32_t a2, uint32_t a3,
    uint32_t b0, uint32_t b1)
{
    asm volatile(
        "mma.sync.aligned.m16n8k16.row.col.f32.f16.f16.f32 "
        "{%0,%1,%2,%3}, {%4,%5,%6,%7}, {%8,%9}, {%0,%1,%2,%3};"
        : "+f"(c[0]), "+f"(c[1]), "+f"(c[2]), "+f"(c[3])
        : "r"(a0), "r"(a1), "r"(a2), "r"(a3), "r"(b0), "r"(b1));
}

// Single-level sense-reversing grid barrier (R1-proven pattern).
__device__ __forceinline__ void grid_barrier() {
    __syncthreads();
    if (threadIdx.x == 0) {
        __threadfence();
        unsigned int g = g_gen;
        if (atomicAdd(&g_cnt, 1u) == NBLK - 1u) {
            g_cnt = 0u;
            __threadfence();
            g_gen = g + 1u;
        } else {
            while (g_gen == g) { }
        }
        __threadfence();
    }
    __syncthreads();
}

// =====================================================================
// Packing converters (fp32 -> fp16 mma fragments)
// A slot s = ((mb*64+kt)*8+rg)*32+lane : uint4 {a0,a1,a2,a3} for
//   rows mb*128+rg*16+{g,g+8}, k = kt*16+{2tig,2tig+1,8+2tig,9+2tig}
// =====================================================================
__global__ void __launch_bounds__(256) conv_pack_a(
    const float* __restrict__ X, uint4* __restrict__ Ap)
{
    int s = blockIdx.x * 256 + threadIdx.x;
    int lane = s & 31, rg = (s >> 5) & 7, kt = (s >> 8) & 63, mb = s >> 14;
    int g = lane >> 2, tig = lane & 3;
    int r0 = mb * 128 + rg * 16 + g;
    int k0 = kt * 16 + 2 * tig;
    const float* p0 = X + (size_t)r0 * HH;
    const float* p1 = X + (size_t)(r0 + 8) * HH;
    uint4 v;
    v.x = h2pack(p0[k0],     p0[k0 + 1]);
    v.y = h2pack(p1[k0],     p1[k0 + 1]);
    v.z = h2pack(p0[k0 + 8], p0[k0 + 9]);
    v.w = h2pack(p1[k0 + 8], p1[k0 + 9]);
    Ap[s] = v;
}

// B slot (uint2) s = ((nb*64+kt)*16+cg)*32+lane :
//   n = nb*128+cg*8+g, b0 = {W[n][kt*16+2tig], +1}, b1 = {+8, +9}
__global__ void __launch_bounds__(256) conv_pack_b(
    const float* __restrict__ W, uint2* __restrict__ Bp)
{
    int s = blockIdx.x * 256 + threadIdx.x;
    int lane = s & 31, cg = (s >> 5) & 15, kt = (s >> 9) & 63, nb = s >> 15;
    int g = lane >> 2, tig = lane & 3;
    int n  = nb * 128 + cg * 8 + g;
    int k0 = kt * 16 + 2 * tig;
    const float* p = W + (size_t)n * HH;
    Bp[s] = make_uint2(h2pack(p[k0], p[k0 + 1]), h2pack(p[k0 + 8], p[k0 + 9]));
}

// =====================================================================
// Input projection GEMM, fp16 tensor cores, cp.async 8-deep smem pipeline
// with PROPER TAIL DRAIN (fixes the stale-stage race of R9-R11).
//   Y[m][n] = sum_k X[m][k]*W[n][k] + bi[n],  M=16384, N=4096, K=1024
//   512 threads, 16 warps (wm 0..3 x wn 0..3), warp tile 32x32.
//   smem: 8 stages x (A 4KB + B 4KB) = 64KB dynamic.
// =====================================================================
#define STG 8
#define GEMM_SMEM (STG * 512 * 16)

__global__ void __launch_bounds__(512, 1) gemm_h(
    const uint4* __restrict__ Ap, const uint4* __restrict__ Bp4,
    const float* __restrict__ bi, float* __restrict__ Y)
{
    extern __shared__ uint4 sm[];   // [stage*512 + (A:0..255 | B:256..511)]

    const int tid  = threadIdx.x;
    const int warp = tid >> 5;
    const int lane = tid & 31;
    const int wm   = warp >> 2;
    const int wn   = warp & 3;
    const int nb   = blockIdx.x;
    const int mb   = blockIdx.y;

    const uint4* Ab4 = Ap  + (size_t)mb * 16384;
    const uint4* Bb4 = Bp4 + (size_t)nb * 16384;

    // per-thread cp.async source/dest partition
    const int j = tid & 255;
    const bool isA = tid < 256;
    const uint4* srcBase = isA ? Ab4 : Bb4;
    const int dstOff = (isA ? 0 : 256) + j;

    float C[2][4][4];
#pragma unroll
    for (int a = 0; a < 2; ++a)
#pragma unroll
        for (int b = 0; b < 4; ++b)
#pragma unroll
            for (int c = 0; c < 4; ++c) C[a][b][c] = 0.0f;

#define ISSUE(kt)                                                                   \
    {                                                                               \
        uint32_t d = (uint32_t)__cvta_generic_to_shared(                            \
            &sm[((kt) & (STG - 1)) * 512 + dstOff]);                                \
        const uint4* s_ = srcBase + (size_t)(kt) * 256 + j;                         \
        asm volatile("cp.async.cg.shared.global [%0], [%1], 16;\n" :: "r"(d), "l"(s_)); \
        asm volatile("cp.async.commit_group;\n");                                   \
    }

#define COMPUTE(kt)                                                                 \
    {                                                                               \
        const int st = (kt) & (STG - 1);                                            \
        uint4 au[2];                                                                \
        _Pragma("unroll")                                                           \
        for (int mt = 0; mt < 2; ++mt)                                              \
            au[mt] = sm[st * 512 + (wm * 2 + mt) * 32 + lane];                      \
        const uint2* b2 = (const uint2*)(sm + st * 512 + 256);                      \
        uint2 bu[4];                                                                \
        _Pragma("unroll")                                                           \
        for (int cg = 0; cg < 4; ++cg)                                              \
            bu[cg] = b2[(wn * 4 + cg) * 32 + lane];                                 \
        _Pragma("unroll")                                                           \
        for (int mt = 0; mt < 2; ++mt)                                              \
            _Pragma("unroll")                                                       \
            for (int cg = 0; cg < 4; ++cg)                                          \
                mma16816(C[mt][cg], au[mt].x, au[mt].y, au[mt].z, au[mt].w,         \
                         bu[cg].x, bu[cg].y);                                       \
    }

    // prologue: stages 0..6 in flight
#pragma unroll
    for (int kt = 0; kt < STG - 1; ++kt) ISSUE(kt);

    // main loop: kt in [0, 57). Pending at entry is exactly 7 groups, so
    // wait_group 6 PROVES group kt complete before the reads.
#pragma unroll 1
    for (int kt = 0; kt < 64 - (STG - 1); ++kt) {
        asm volatile("cp.async.wait_group %0;\n" :: "n"(STG - 2) : "memory");
        __syncthreads();
        ISSUE(kt + STG - 1);
        COMPUTE(kt);
    }

    // tail: drain EVERYTHING, then consume the last 7 distinct stages.
    asm volatile("cp.async.wait_group 0;\n" ::: "memory");
    __syncthreads();
#pragma unroll
    for (int kt = 64 - (STG - 1); kt < 64; ++kt) {
        COMPUTE(kt);
    }
#undef ISSUE
#undef COMPUTE

    const int g = lane >> 2, tig = lane & 3;
#pragma unroll
    for (int mt = 0; mt < 2; ++mt) {
#pragma unroll
        for (int cg = 0; cg < 4; ++cg) {
            int row = mb * 128 + wm * 32 + mt * 16 + g;
            int col = nb * 128 + wn * 32 + cg * 8 + 2 * tig;
            float b0 = bi[col], b1 = bi[col + 1];
            *(float2*)(Y + (size_t)row * G4H + col) =
                make_float2(C[mt][cg][0] + b0, C[mt][cg][1] + b1);
            *(float2*)(Y + (size_t)(row + 8) * G4H + col) =
                make_float2(C[mt][cg][2] + b0, C[mt][cg][3] + b1);
        }
    }
}

// =====================================================================
// Persistent recurrent kernel: 256 threads / 8 warps, fp16 operands.
// Block owns 8 n-indices -> 32 gate columns. Warp w: k in [w*128,(w+1)*128),
// 8 mma-ksteps of 16. R fp16 fragments register-resident (64 regs).
// All 16 h fragments burst-prefetched (MLP=16, one L2 latency exposure).
// =====================================================================
__global__ void __launch_bounds__(256, 1) recurrent_h(
    const float* __restrict__ xg,   // [T][B][4H]
    const float* __restrict__ R,    // [4H][H]
    const float* __restrict__ bh,   // [4H]
    const float* __restrict__ h0,   // [B][H]
    const float* __restrict__ c0,   // [B][H]
    float* __restrict__ outp,
    float* __restrict__ hT,         // [B][H]
    float* __restrict__ cT,         // [B][H]
    int mode)
{
    __shared__ float part[32 * 296];   // part[b][w][j] : b*296 + w*37 + j

    const int tid  = threadIdx.x;
    const int w    = tid >> 5;
    const int lane = tid & 31;
    const int g    = lane >> 2;
    const int tig  = lane & 3;
    const int n0   = blockIdx.x * 8;

    // ---- Preload R fp16 B-fragments into registers ----
    uint32_t Br[4][8][2];
#pragma unroll
    for (int cg = 0; cg < 4; ++cg) {
        const float* rp = R + (size_t)(cg * HH + n0 + g) * HH + w * 128 + 2 * tig;
#pragma unroll
        for (int ks = 0; ks < 8; ++ks) {
            const float* q = rp + ks * 16;
            Br[cg][ks][0] = h2pack(__ldg(q),     __ldg(q + 1));
            Br[cg][ks][1] = h2pack(__ldg(q + 8), __ldg(q + 9));
        }
    }

    // ---- Convert h0 into packed fp16 HB[0] (32 slots per block) ----
    if (tid < 32) {
        int slot = blockIdx.x * 32 + tid;            // 0..4095
        int ls = slot & 31, mts = (slot >> 5) & 1, kt = slot >> 6;
        int gs = ls >> 2, ts = ls & 3;
        int r0 = mts * 16 + gs;
        int k0 = kt * 16 + 2 * ts;
        const float* p0 = h0 + (size_t)r0 * HH;
        const float* p1 = h0 + (size_t)(r0 + 8) * HH;
        uint4 v;
        v.x = h2pack(p0[k0],     p0[k0 + 1]);
        v.y = h2pack(p1[k0],     p1[k0 + 1]);
        v.z = h2pack(p0[k0 + 8], p0[k0 + 9]);
        v.w = h2pack(p1[k0 + 8], p1[k0 + 9]);
        g_hb[0][slot] = v;
    }

    // ---- update-phase constants ----
    const int ub = tid >> 3;   // b 0..31
    const int un = tid & 7;    // n-offset 0..7
    const int hid = n0 + un;
    float bhv[4];
#pragma unroll
    for (int gg = 0; gg < 4; ++gg) bhv[gg] = bh[gg * HH + hid];
    float creg = c0[ub * HH + hid];

    // fp16 h write address for (ub, hid) inside HB slot
    const int hw_mt = ub >> 4, hw_row16 = ub & 15;
    const int hw_g = hw_row16 & 7, hw_rh = hw_row16 >> 3;
    const int hw_kt = hid >> 4, hw_k15 = hid & 15;
    const int hw_kh = hw_k15 >> 3, hw_tig = (hw_k15 & 7) >> 1, hw_hs = hw_k15 & 1;
    const int hb_slot = (hw_kt * 2 + hw_mt) * 32 + hw_g * 4 + hw_tig;
    const int hb_half = (hw_kh * 2 + hw_rh) * 2 + hw_hs;   // half index within uint4
    __half* hb_w[2] = { (__half*)&g_hb[0][hb_slot] + hb_half,
                        (__half*)&g_hb[1][hb_slot] + hb_half };

    grid_barrier();   // HB[0] ready everywhere

    for (int t = 0; t < TT; ++t) {
        const uint4* hp = g_hb[t & 1];

        // Burst-prefetch ALL 16 h fragments (MLP=16, one L2 latency exposure)
        uint4 Ab[8][2];
#pragma unroll
        for (int p = 0; p < 8; ++p)
#pragma unroll
            for (int mt = 0; mt < 2; ++mt)
                Ab[p][mt] = __ldcg(&hp[((w * 8 + p) * 2 + mt) * 32 + lane]);

        // prefetch xg for update phase (latency hidden behind mma)
        const float* xgt = xg + ((size_t)t * BB + ub) * G4H + hid;
        float xv[4];
#pragma unroll
        for (int gg = 0; gg < 4; ++gg) xv[gg] = __ldg(xgt + gg * HH);

        float Cr[2][4][4];
#pragma unroll
        for (int a = 0; a < 2; ++a)
#pragma unroll
            for (int b = 0; b < 4; ++b)
#pragma unroll
                for (int c = 0; c < 4; ++c) Cr[a][b][c] = 0.0f;

#pragma unroll
        for (int ks = 0; ks < 8; ++ks) {
            uint4 a0 = Ab[ks][0];
            uint4 a1 = Ab[ks][1];
#pragma unroll
            for (int cg = 0; cg < 4; ++cg) {
                mma16816(Cr[0][cg], a0.x, a0.y, a0.z, a0.w, Br[cg][ks][0], Br[cg][ks][1]);
                mma16816(Cr[1][cg], a1.x, a1.y, a1.z, a1.w, Br[cg][ks][0], Br[cg][ks][1]);
            }
        }

        // store partials to smem (SCALAR stores: stride 37 is odd -> no float2)
#pragma unroll
        for (int mt = 0; mt < 2; ++mt) {
#pragma unroll
            for (int cg = 0; cg < 4; ++cg) {
                int b = mt * 16 + g;
                int jj = cg * 8 + 2 * tig;
                part[b * 296 + w * 37 + jj]           = Cr[mt][cg][0];
                part[b * 296 + w * 37 + jj + 1]       = Cr[mt][cg][1];
                part[(b + 8) * 296 + w * 37 + jj]     = Cr[mt][cg][2];
                part[(b + 8) * 296 + w * 37 + jj + 1] = Cr[mt][cg][3];
            }
        }
        __syncthreads();

        // reduce over 8 warps + gate math. gates order: i, o, z, f
        float gate[4];
#pragma unroll
        for (int gg = 0; gg < 4; ++gg) {
            float s = xv[gg] + bhv[gg];
#pragma unroll
            for (int wi = 0; wi < 8; ++wi)
                s += part[ub * 296 + wi * 37 + gg * 8 + un];
            gate[gg] = sigm(s);
        }
        creg = creg * gate[3] + gate[2] - gate[0];   // c = c*f + z - i
        float hval = sigm(creg) - gate[1];           // h = sigm(c) - o

        if (mode == 0) {
            // packed-A fp16 layout for layer-1 gemm
            int m = t * BB + ub;
            int mb = m >> 7, r = m & 127;
            int rg_ = r >> 4, row16 = r & 15;
            int g_ = row16 & 7, rh_ = row16 >> 3;
            size_t slot = ((size_t)(mb * 64 + hw_kt) * 8 + rg_) * 32 + g_ * 4 + hw_tig;
            ((__half*)&((uint4*)outp)[slot])[(hw_kh * 2 + rh_) * 2 + hw_hs] =
                __float2half_rn(hval);
        } else {
            outp[((size_t)t * BB + ub) * HH + hid] = hval;
        }

        // fp16 HB store for next step
        *hb_w[(t + 1) & 1] = __float2half_rn(hval);

        if (t == TT - 1) {
            hT[ub * HH + hid] = hval;
            cT[ub * HH + hid] = creg;
        }

        grid_barrier();
    }
}

// ---------------- launch ----------------
extern "C" void kernel_launch(void* const* d_in, const int* in_sizes, int n_in,
                              void* d_out, int out_size)
{
    (void)in_sizes; (void)n_in; (void)out_size;
    const float* x   = (const float*)d_in[0];
    const float* h0  = (const float*)d_in[1];
    const float* c0  = (const float*)d_in[2];
    const float* W0  = (const float*)d_in[3];
    const float* R0  = (const float*)d_in[4];
    const float* bi0 = (const float*)d_in[5];
    const float* bh0 = (const float*)d_in[6];
    const float* W1  = (const float*)d_in[7];
    const float* R1  = (const float*)d_in[8];
    const float* bi1 = (const float*)d_in[9];
    const float* bh1 = (const float*)d_in[10];

    float* out = (float*)d_out;
    float* hT  = out + (size_t)TT * BB * HH;
    float* cT  = hT + (size_t)2 * BB * HH;

    float* xg = nullptr;  cudaGetSymbolAddress((void**)&xg, g_xg);
    uint4* xa = nullptr;  cudaGetSymbolAddress((void**)&xa, g_xa);
    uint4* x1 = nullptr;  cudaGetSymbolAddress((void**)&x1, g_x1);
    uint4* wb = nullptr;  cudaGetSymbolAddress((void**)&wb, g_wb);

    cudaFuncSetAttribute(gemm_h, cudaFuncAttributeMaxDynamicSharedMemorySize, GEMM_SMEM);

    dim3 ggrid(G4H / 128, (TT * BB) / 128);  // (32, 128)

    // Layer 0
    conv_pack_a<<<2097152 / 256, 256>>>(x, xa);
    conv_pack_b<<<1048576 / 256, 256>>>(W0, (uint2*)wb);
    gemm_h<<<ggrid, 512, GEMM_SMEM>>>(xa, wb, bi0, xg);
    recurrent_h<<<NBLK, 256>>>(xg, R0, bh0, h0, c0, (float*)x1, hT, cT, 0);
    // Layer 1
    conv_pack_b<<<1048576 / 256, 256>>>(W1, (uint2*)wb);
    gemm_h<<<ggrid, 512, GEMM_SMEM>>>(x1, wb, bi1, xg);
    recurrent_h<<<NBLK, 256>>>(xg, R1, bh1, h0 + BB * HH, c0 + BB * HH,
                               out, hT + BB * HH, cT + BB * HH, 1);
}

// round 13
// speedup vs baseline: 1.1122x; 1.0267x over previous
#include <cuda_runtime.h>
#include <cuda_fp16.h>
#include <cstdint>
#include <cstddef>

// Problem constants
#define TT   512
#define BB   32
#define HH   1024
#define G4H  4096
#define NBLK 128           // persistent recurrent grid (co-resident)

// ---------------- scratch ----------------
__device__ float g_xg[(size_t)TT * BB * G4H];     // input projection (fp32 [t][b][4H])
__device__ uint4 g_xa[2097152];                   // packed-A fp16 X (layer 0), 32MB
__device__ uint4 g_x1[2097152];                   // packed-A fp16 layer-0 output, 32MB
__device__ uint4 g_wb[1048576];                   // packed-B fp16 weights (16MB), per layer
__device__ uint4 g_hb[2][4096];                   // packed-A fp16 hidden state, ping-pong (2x64KB)
__device__ unsigned int          g_cnt;
__device__ volatile unsigned int g_gen;

__device__ __forceinline__ float sigm(float x) {
    return 1.0f / (1.0f + expf(-x));
}

// pack two floats into one fp16x2 register (lo = first arg)
__device__ __forceinline__ uint32_t h2pack(float lo, float hi) {
    __half2 h = __floats2half2_rn(lo, hi);
    return *(uint32_t*)&h;
}

// fp16 tensor-core mma, fp32 accumulate
__device__ __forceinline__ void mma16816(float c[4],
    uint32_t a0, uint32_t a1, uint32_t a2, uint32_t a3,
    uint32_t b0, uint32_t b1)
{
    asm volatile(
        "mma.sync.aligned.m16n8k16.row.col.f32.f16.f16.f32 "
        "{%0,%1,%2,%3}, {%4,%5,%6,%7}, {%8,%9}, {%0,%1,%2,%3};"
        : "+f"(c[0]), "+f"(c[1]), "+f"(c[2]), "+f"(c[3])
        : "r"(a0), "r"(a1), "r"(a2), "r"(a3), "r"(b0), "r"(b1));
}

// Single-level sense-reversing grid barrier (R1-proven pattern).
__device__ __forceinline__ void grid_barrier() {
    __syncthreads();
    if (threadIdx.x == 0) {
        __threadfence();
        unsigned int g = g_gen;
        if (atomicAdd(&g_cnt, 1u) == NBLK - 1u) {
            g_cnt = 0u;
            __threadfence();
            g_gen = g + 1u;
        } else {
            while (g_gen == g) { }
        }
        __threadfence();
    }
    __syncthreads();
}

// =====================================================================
// Packing converters (fp32 -> fp16 mma fragments)
// A slot s = ((mb*64+kt)*8+rg)*32+lane : uint4 {a0,a1,a2,a3} for
//   rows mb*128+rg*16+{g,g+8}, k = kt*16+{2tig,2tig+1,8+2tig,9+2tig}
// =====================================================================
__global__ void __launch_bounds__(256) conv_pack_a(
    const float* __restrict__ X, uint4* __restrict__ Ap)
{
    int s = blockIdx.x * 256 + threadIdx.x;
    int lane = s & 31, rg = (s >> 5) & 7, kt = (s >> 8) & 63, mb = s >> 14;
    int g = lane >> 2, tig = lane & 3;
    int r0 = mb * 128 + rg * 16 + g;
    int k0 = kt * 16 + 2 * tig;
    const float* p0 = X + (size_t)r0 * HH;
    const float* p1 = X + (size_t)(r0 + 8) * HH;
    uint4 v;
    v.x = h2pack(p0[k0],     p0[k0 + 1]);
    v.y = h2pack(p1[k0],     p1[k0 + 1]);
    v.z = h2pack(p0[k0 + 8], p0[k0 + 9]);
    v.w = h2pack(p1[k0 + 8], p1[k0 + 9]);
    Ap[s] = v;
}

// B slot (uint2) s = ((nb*64+kt)*16+cg)*32+lane :
//   n = nb*128+cg*8+g, b0 = {W[n][kt*16+2tig], +1}, b1 = {+8, +9}
__global__ void __launch_bounds__(256) conv_pack_b(
    const float* __restrict__ W, uint2* __restrict__ Bp)
{
    int s = blockIdx.x * 256 + threadIdx.x;
    int lane = s & 31, cg = (s >> 5) & 15, kt = (s >> 9) & 63, nb = s >> 15;
    int g = lane >> 2, tig = lane & 3;
    int n  = nb * 128 + cg * 8 + g;
    int k0 = kt * 16 + 2 * tig;
    const float* p = W + (size_t)n * HH;
    Bp[s] = make_uint2(h2pack(p[k0], p[k0 + 1]), h2pack(p[k0 + 8], p[k0 + 9]));
}

// =====================================================================
// Input projection GEMM, 256x128 tile, fp16 tensor cores,
// cp.async 8-deep smem pipeline with proper tail drain.
//   Y[m][n] = sum_k X[m][k]*W[n][k] + bi[n],  M=16384, N=4096, K=1024
//   512 threads, 16 warps (wm 0..3 x wn 0..3), warp tile 64x32.
//   Stage = A 8KB (512 uint4) + B 4KB (256 uint4) = 12KB; 8 stages = 96KB.
//   Grid (nb=32, mbBig=64) = 2048 blocks.
// =====================================================================
#define STG 8
#define STAGE_U4 768
#define GEMM_SMEM (STG * STAGE_U4 * 16)   // 98304 bytes

__global__ void __launch_bounds__(512, 1) gemm_h(
    const uint4* __restrict__ Ap, const uint4* __restrict__ Bp4,
    const float* __restrict__ bi, float* __restrict__ Y)
{
    extern __shared__ uint4 sm[];   // [stage*768 + (A:0..511 | B:512..767)]

    const int tid  = threadIdx.x;
    const int warp = tid >> 5;
    const int lane = tid & 31;
    const int wm   = warp >> 2;      // 0..3 (m, 64 rows each)
    const int wn   = warp & 3;       // 0..3 (n, 32 cols each)
    const int nb   = blockIdx.x;
    const int mbBig = blockIdx.y;    // 256-row block

    // A source for this thread: rgBig in [0,16) spans two 128-row packed blocks
    const int a_rgBig = (tid >> 5) & 15;
    const int a_mb128 = 2 * mbBig + (a_rgBig >> 3);
    const uint4* a_src_base = Ap + (size_t)a_mb128 * 16384 + ((size_t)(a_rgBig & 7)) * 32 + lane;
    // per kt: a_src = a_src_base + kt*8*32  (slot stride of kt is 8*32)

    // B source (uint4 view): per kt 256 uint4 starting at (nb*64+kt)*256
    const uint4* b_src_base = Bp4 + (size_t)nb * 16384 + (tid & 255);
    const bool hasB = tid < 256;

    float C[4][4][4];
#pragma unroll
    for (int a = 0; a < 4; ++a)
#pragma unroll
        for (int b = 0; b < 4; ++b)
#pragma unroll
            for (int c = 0; c < 4; ++c) C[a][b][c] = 0.0f;

#define ISSUE(kt)                                                                     \
    {                                                                                 \
        uint32_t da = (uint32_t)__cvta_generic_to_shared(                             \
            &sm[((kt) & (STG - 1)) * STAGE_U4 + tid]);                                \
        const uint4* sa_ = a_src_base + (size_t)(kt) * 256;                           \
        asm volatile("cp.async.cg.shared.global [%0], [%1], 16;\n" :: "r"(da), "l"(sa_)); \
        if (hasB) {                                                                   \
            uint32_t db = (uint32_t)__cvta_generic_to_shared(                         \
                &sm[((kt) & (STG - 1)) * STAGE_U4 + 512 + (tid & 255)]);              \
            const uint4* sb_ = b_src_base + (size_t)(kt) * 256;                       \
            asm volatile("cp.async.cg.shared.global [%0], [%1], 16;\n" :: "r"(db), "l"(sb_)); \
        }                                                                             \
        asm volatile("cp.async.commit_group;\n");                                     \
    }

#define COMPUTE(kt)                                                                   \
    {                                                                                 \
        const int st = (kt) & (STG - 1);                                              \
        uint4 au[4];                                                                  \
        _Pragma("unroll")                                                             \
        for (int mt = 0; mt < 4; ++mt)                                                \
            au[mt] = sm[st * STAGE_U4 + (wm * 4 + mt) * 32 + lane];                   \
        const uint2* b2 = (const uint2*)(sm + st * STAGE_U4 + 512);                   \
        uint2 bu[4];                                                                  \
        _Pragma("unroll")                                                             \
        for (int cg = 0; cg < 4; ++cg)                                                \
            bu[cg] = b2[(wn * 4 + cg) * 32 + lane];                                   \
        _Pragma("unroll")                                                             \
        for (int mt = 0; mt < 4; ++mt)                                                \
            _Pragma("unroll")                                                         \
            for (int cg = 0; cg < 4; ++cg)                                            \
                mma16816(C[mt][cg], au[mt].x, au[mt].y, au[mt].z, au[mt].w,           \
                         bu[cg].x, bu[cg].y);                                         \
    }

    // prologue: stages 0..6 in flight
#pragma unroll
    for (int kt = 0; kt < STG - 1; ++kt) ISSUE(kt);

    // main loop: pending at entry is exactly 7 groups -> wait_group 6 proves
    // group kt complete before reads.
#pragma unroll 1
    for (int kt = 0; kt < 64 - (STG - 1); ++kt) {
        asm volatile("cp.async.wait_group %0;\n" :: "n"(STG - 2) : "memory");
        __syncthreads();
        ISSUE(kt + STG - 1);
        COMPUTE(kt);
    }

    // tail: drain everything, then consume the last 7 distinct stages.
    asm volatile("cp.async.wait_group 0;\n" ::: "memory");
    __syncthreads();
#pragma unroll
    for (int kt = 64 - (STG - 1); kt < 64; ++kt) {
        COMPUTE(kt);
    }
#undef ISSUE
#undef COMPUTE

    const int g = lane >> 2, tig = lane & 3;
#pragma unroll
    for (int mt = 0; mt < 4; ++mt) {
#pragma unroll
        for (int cg = 0; cg < 4; ++cg) {
            int row = mbBig * 256 + wm * 64 + mt * 16 + g;
            int col = nb * 128 + wn * 32 + cg * 8 + 2 * tig;
            float b0 = bi[col], b1 = bi[col + 1];
            *(float2*)(Y + (size_t)row * G4H + col) =
                make_float2(C[mt][cg][0] + b0, C[mt][cg][1] + b1);
            *(float2*)(Y + (size_t)(row + 8) * G4H + col) =
                make_float2(C[mt][cg][2] + b0, C[mt][cg][3] + b1);
        }
    }
}

// =====================================================================
// Persistent recurrent kernel — EXACT R12 version (known good).
// 256 threads / 8 warps, fp16 operands, R register-resident,
// burst-prefetch of all 16 h fragments, scalar partial stores.
// =====================================================================
__global__ void __launch_bounds__(256, 1) recurrent_h(
    const float* __restrict__ xg,   // [T][B][4H]
    const float* __restrict__ R,    // [4H][H]
    const float* __restrict__ bh,   // [4H]
    const float* __restrict__ h0,   // [B][H]
    const float* __restrict__ c0,   // [B][H]
    float* __restrict__ outp,
    float* __restrict__ hT,         // [B][H]
    float* __restrict__ cT,         // [B][H]
    int mode)
{
    __shared__ float part[32 * 296];   // part[b][w][j] : b*296 + w*37 + j

    const int tid  = threadIdx.x;
    const int w    = tid >> 5;
    const int lane = tid & 31;
    const int g    = lane >> 2;
    const int tig  = lane & 3;
    const int n0   = blockIdx.x * 8;

    // ---- Preload R fp16 B-fragments into registers ----
    uint32_t Br[4][8][2];
#pragma unroll
    for (int cg = 0; cg < 4; ++cg) {
        const float* rp = R + (size_t)(cg * HH + n0 + g) * HH + w * 128 + 2 * tig;
#pragma unroll
        for (int ks = 0; ks < 8; ++ks) {
            const float* q = rp + ks * 16;
            Br[cg][ks][0] = h2pack(__ldg(q),     __ldg(q + 1));
            Br[cg][ks][1] = h2pack(__ldg(q + 8), __ldg(q + 9));
        }
    }

    // ---- Convert h0 into packed fp16 HB[0] (32 slots per block) ----
    if (tid < 32) {
        int slot = blockIdx.x * 32 + tid;            // 0..4095
        int ls = slot & 31, mts = (slot >> 5) & 1, kt = slot >> 6;
        int gs = ls >> 2, ts = ls & 3;
        int r0 = mts * 16 + gs;
        int k0 = kt * 16 + 2 * ts;
        const float* p0 = h0 + (size_t)r0 * HH;
        const float* p1 = h0 + (size_t)(r0 + 8) * HH;
        uint4 v;
        v.x = h2pack(p0[k0],     p0[k0 + 1]);
        v.y = h2pack(p1[k0],     p1[k0 + 1]);
        v.z = h2pack(p0[k0 + 8], p0[k0 + 9]);
        v.w = h2pack(p1[k0 + 8], p1[k0 + 9]);
        g_hb[0][slot] = v;
    }

    // ---- update-phase constants ----
    const int ub = tid >> 3;   // b 0..31
    const int un = tid & 7;    // n-offset 0..7
    const int hid = n0 + un;
    float bhv[4];
#pragma unroll
    for (int gg = 0; gg < 4; ++gg) bhv[gg] = bh[gg * HH + hid];
    float creg = c0[ub * HH + hid];

    // fp16 h write address for (ub, hid) inside HB slot
    const int hw_mt = ub >> 4, hw_row16 = ub & 15;
    const int hw_g = hw_row16 & 7, hw_rh = hw_row16 >> 3;
    const int hw_kt = hid >> 4, hw_k15 = hid & 15;
    const int hw_kh = hw_k15 >> 3, hw_tig = (hw_k15 & 7) >> 1, hw_hs = hw_k15 & 1;
    const int hb_slot = (hw_kt * 2 + hw_mt) * 32 + hw_g * 4 + hw_tig;
    const int hb_half = (hw_kh * 2 + hw_rh) * 2 + hw_hs;   // half index within uint4
    __half* hb_w[2] = { (__half*)&g_hb[0][hb_slot] + hb_half,
                        (__half*)&g_hb[1][hb_slot] + hb_half };

    grid_barrier();   // HB[0] ready everywhere

    for (int t = 0; t < TT; ++t) {
        const uint4* hp = g_hb[t & 1];

        // Burst-prefetch ALL 16 h fragments (MLP=16, one L2 latency exposure)
        uint4 Ab[8][2];
#pragma unroll
        for (int p = 0; p < 8; ++p)
#pragma unroll
            for (int mt = 0; mt < 2; ++mt)
                Ab[p][mt] = __ldcg(&hp[((w * 8 + p) * 2 + mt) * 32 + lane]);

        // prefetch xg for update phase (latency hidden behind mma)
        const float* xgt = xg + ((size_t)t * BB + ub) * G4H + hid;
        float xv[4];
#pragma unroll
        for (int gg = 0; gg < 4; ++gg) xv[gg] = __ldg(xgt + gg * HH);

        float Cr[2][4][4];
#pragma unroll
        for (int a = 0; a < 2; ++a)
#pragma unroll
            for (int b = 0; b < 4; ++b)
#pragma unroll
                for (int c = 0; c < 4; ++c) Cr[a][b][c] = 0.0f;

#pragma unroll
        for (int ks = 0; ks < 8; ++ks) {
            uint4 a0 = Ab[ks][0];
            uint4 a1 = Ab[ks][1];
#pragma unroll
            for (int cg = 0; cg < 4; ++cg) {
                mma16816(Cr[0][cg], a0.x, a0.y, a0.z, a0.w, Br[cg][ks][0], Br[cg][ks][1]);
                mma16816(Cr[1][cg], a1.x, a1.y, a1.z, a1.w, Br[cg][ks][0], Br[cg][ks][1]);
            }
        }

        // store partials to smem (SCALAR stores: stride 37 is odd -> no float2)
#pragma unroll
        for (int mt = 0; mt < 2; ++mt) {
#pragma unroll
            for (int cg = 0; cg < 4; ++cg) {
                int b = mt * 16 + g;
                int jj = cg * 8 + 2 * tig;
                part[b * 296 + w * 37 + jj]           = Cr[mt][cg][0];
                part[b * 296 + w * 37 + jj + 1]       = Cr[mt][cg][1];
                part[(b + 8) * 296 + w * 37 + jj]     = Cr[mt][cg][2];
                part[(b + 8) * 296 + w * 37 + jj + 1] = Cr[mt][cg][3];
            }
        }
        __syncthreads();

        // reduce over 8 warps + gate math. gates order: i, o, z, f
        float gate[4];
#pragma unroll
        for (int gg = 0; gg < 4; ++gg) {
            float s = xv[gg] + bhv[gg];
#pragma unroll
            for (int wi = 0; wi < 8; ++wi)
                s += part[ub * 296 + wi * 37 + gg * 8 + un];
            gate[gg] = sigm(s);
        }
        creg = creg * gate[3] + gate[2] - gate[0];   // c = c*f + z - i
        float hval = sigm(creg) - gate[1];           // h = sigm(c) - o

        if (mode == 0) {
            // packed-A fp16 layout for layer-1 gemm
            int m = t * BB + ub;
            int mb = m >> 7, r = m & 127;
            int rg_ = r >> 4, row16 = r & 15;
            int g_ = row16 & 7, rh_ = row16 >> 3;
            size_t slot = ((size_t)(mb * 64 + hw_kt) * 8 + rg_) * 32 + g_ * 4 + hw_tig;
            ((__half*)&((uint4*)outp)[slot])[(hw_kh * 2 + rh_) * 2 + hw_hs] =
                __float2half_rn(hval);
        } else {
            outp[((size_t)t * BB + ub) * HH + hid] = hval;
        }

        // fp16 HB store for next step
        *hb_w[(t + 1) & 1] = __float2half_rn(hval);

        if (t == TT - 1) {
            hT[ub * HH + hid] = hval;
            cT[ub * HH + hid] = creg;
        }

        grid_barrier();
    }
}

// ---------------- launch ----------------
extern "C" void kernel_launch(void* const* d_in, const int* in_sizes, int n_in,
                              void* d_out, int out_size)
{
    (void)in_sizes; (void)n_in; (void)out_size;
    const float* x   = (const float*)d_in[0];
    const float* h0  = (const float*)d_in[1];
    const float* c0  = (const float*)d_in[2];
    const float* W0  = (const float*)d_in[3];
    const float* R0  = (const float*)d_in[4];
    const float* bi0 = (const float*)d_in[5];
    const float* bh0 = (const float*)d_in[6];
    const float* W1  = (const float*)d_in[7];
    const float* R1  = (const float*)d_in[8];
    const float* bi1 = (const float*)d_in[9];
    const float* bh1 = (const float*)d_in[10];

    float* out = (float*)d_out;
    float* hT  = out + (size_t)TT * BB * HH;
    float* cT  = hT + (size_t)2 * BB * HH;

    float* xg = nullptr;  cudaGetSymbolAddress((void**)&xg, g_xg);
    uint4* xa = nullptr;  cudaGetSymbolAddress((void**)&xa, g_xa);
    uint4* x1 = nullptr;  cudaGetSymbolAddress((void**)&x1, g_x1);
    uint4* wb = nullptr;  cudaGetSymbolAddress((void**)&wb, g_wb);

    cudaFuncSetAttribute(gemm_h, cudaFuncAttributeMaxDynamicSharedMemorySize, GEMM_SMEM);

    dim3 ggrid(G4H / 128, (TT * BB) / 256);  // (32, 64)

    // Layer 0
    conv_pack_a<<<2097152 / 256, 256>>>(x, xa);
    conv_pack_b<<<1048576 / 256, 256>>>(W0, (uint2*)wb);
    gemm_h<<<ggrid, 512, GEMM_SMEM>>>(xa, wb, bi0, xg);
    recurrent_h<<<NBLK, 256>>>(xg, R0, bh0, h0, c0, (float*)x1, hT, cT, 0);
    // Layer 1
    conv_pack_b<<<1048576 / 256, 256>>>(W1, (uint2*)wb);
    gemm_h<<<ggrid, 512, GEMM_SMEM>>>(x1, wb, bi1, xg);
    recurrent_h<<<NBLK, 256>>>(xg, R1, bh1, h0 + BB * HH, c0 + BB * HH,
                               out, hT + BB * HH, cT + BB * HH, 1);
}

// round 16
// speedup vs baseline: 1.2694x; 1.1414x over previous
#include <cuda_runtime.h>
#include <cuda_fp16.h>
#include <cstdint>
#include <cstddef>

// Problem constants
#define TT   512
#define BB   32
#define HH   1024
#define G4H  4096
#define NBLK 128           // persistent recurrent grid (co-resident)

// ---------------- scratch ----------------
__device__ float g_xg[(size_t)TT * BB * G4H];     // input projection (fp32 [t][b][4H])
__device__ uint4 g_xa[2097152];                   // packed-A fp16 X (layer 0), 32MB
__device__ uint4 g_x1[2097152];                   // packed-A fp16 layer-0 output, 32MB
__device__ uint4 g_wb[1048576];                   // packed-B fp16 weights (16MB), per layer
__device__ uint4 g_hb[2][4096];                   // packed-A fp16 hidden state, ping-pong (2x64KB)
__device__ unsigned int          g_cnt;           // entry barrier counter
__device__ volatile unsigned int g_gen;           // entry barrier generation
__device__ volatile unsigned int g_scnt;          // monotone step counter (reset at entry)

__device__ __forceinline__ float sigm(float x) {
    return 1.0f / (1.0f + expf(-x));
}

// pack two floats into one fp16x2 register (lo = first arg)
__device__ __forceinline__ uint32_t h2pack(float lo, float hi) {
    __half2 h = __floats2half2_rn(lo, hi);
    return *(uint32_t*)&h;
}

// fp16 tensor-core mma, fp32 accumulate
__device__ __forceinline__ void mma16816(float c[4],
    uint32_t a0, uint32_t a1, uint32_t a2, uint32_t a3,
    uint32_t b0, uint32_t b1)
{
    asm volatile(
        "mma.sync.aligned.m16n8k16.row.col.f32.f16.f16.f32 "
        "{%0,%1,%2,%3}, {%4,%5,%6,%7}, {%8,%9}, {%0,%1,%2,%3};"
        : "+f"(c[0]), "+f"(c[1]), "+f"(c[2]), "+f"(c[3])
        : "r"(a0), "r"(a1), "r"(a2), "r"(a3), "r"(b0), "r"(b1));
}

// Atomic entry barrier (R1-R13 proven pattern). Used once per launch:
// publishes HB[0], R preload visibility, and the g_scnt reset.
__device__ __forceinline__ void grid_barrier_atomic() {
    __syncthreads();
    if (threadIdx.x == 0) {
        __threadfence();
        unsigned int g = g_gen;
        if (atomicAdd(&g_cnt, 1u) == NBLK - 1u) {
            g_cnt = 0u;
            __threadfence();
            g_gen = g + 1u;
        } else {
            while (g_gen == g) { }
        }
        __threadfence();
    }
    __syncthreads();
}

// Monotone-counter step barrier: arrival = RED (atomicAdd, result unused),
// release = direct poll of the counter (volatile load, R1-R13-proven poll
// mechanism). No reset, no releaser hop, no deadlock window.
__device__ __forceinline__ void step_barrier(int t) {
    __syncthreads();
    if (threadIdx.x == 0) {
        __threadfence();
        atomicAdd((unsigned int*)&g_scnt, 1u);
        const unsigned int tgt = (unsigned int)(NBLK * (t + 1));
        while (g_scnt < tgt) { }
        __threadfence();
    }
    __syncthreads();
}

// =====================================================================
// Packing converters (fp32 -> fp16 mma fragments)
// =====================================================================
__global__ void __launch_bounds__(256) conv_pack_a(
    const float* __restrict__ X, uint4* __restrict__ Ap)
{
    int s = blockIdx.x * 256 + threadIdx.x;
    int lane = s & 31, rg = (s >> 5) & 7, kt = (s >> 8) & 63, mb = s >> 14;
    int g = lane >> 2, tig = lane & 3;
    int r0 = mb * 128 + rg * 16 + g;
    int k0 = kt * 16 + 2 * tig;
    const float* p0 = X + (size_t)r0 * HH;
    const float* p1 = X + (size_t)(r0 + 8) * HH;
    uint4 v;
    v.x = h2pack(p0[k0],     p0[k0 + 1]);
    v.y = h2pack(p1[k0],     p1[k0 + 1]);
    v.z = h2pack(p0[k0 + 8], p0[k0 + 9]);
    v.w = h2pack(p1[k0 + 8], p1[k0 + 9]);
    Ap[s] = v;
}

__global__ void __launch_bounds__(256) conv_pack_b(
    const float* __restrict__ W, uint2* __restrict__ Bp)
{
    int s = blockIdx.x * 256 + threadIdx.x;
    int lane = s & 31, cg = (s >> 5) & 15, kt = (s >> 9) & 63, nb = s >> 15;
    int g = lane >> 2, tig = lane & 3;
    int n  = nb * 128 + cg * 8 + g;
    int k0 = kt * 16 + 2 * tig;
    const float* p = W + (size_t)n * HH;
    Bp[s] = make_uint2(h2pack(p[k0], p[k0 + 1]), h2pack(p[k0 + 8], p[k0 + 9]));
}

// =====================================================================
// Input projection GEMM, 256x128 tile, fp16 tensor cores,
// cp.async 8-deep smem pipeline with proper tail drain. (R13, unchanged.)
// =====================================================================
#define STG 8
#define STAGE_U4 768
#define GEMM_SMEM (STG * STAGE_U4 * 16)   // 98304 bytes

__global__ void __launch_bounds__(512, 1) gemm_h(
    const uint4* __restrict__ Ap, const uint4* __restrict__ Bp4,
    const float* __restrict__ bi, float* __restrict__ Y)
{
    extern __shared__ uint4 sm[];   // [stage*768 + (A:0..511 | B:512..767)]

    const int tid  = threadIdx.x;
    const int warp = tid >> 5;
    const int lane = tid & 31;
    const int wm   = warp >> 2;      // 0..3 (m, 64 rows each)
    const int wn   = warp & 3;       // 0..3 (n, 32 cols each)
    const int nb   = blockIdx.x;
    const int mbBig = blockIdx.y;    // 256-row block

    const int a_rgBig = (tid >> 5) & 15;
    const int a_mb128 = 2 * mbBig + (a_rgBig >> 3);
    const uint4* a_src_base = Ap + (size_t)a_mb128 * 16384 + ((size_t)(a_rgBig & 7)) * 32 + lane;
    const uint4* b_src_base = Bp4 + (size_t)nb * 16384 + (tid & 255);
    const bool hasB = tid < 256;

    float C[4][4][4];
#pragma unroll
    for (int a = 0; a < 4; ++a)
#pragma unroll
        for (int b = 0; b < 4; ++b)
#pragma unroll
            for (int c = 0; c < 4; ++c) C[a][b][c] = 0.0f;

#define ISSUE(kt)                                                                     \
    {                                                                                 \
        uint32_t da = (uint32_t)__cvta_generic_to_shared(                             \
            &sm[((kt) & (STG - 1)) * STAGE_U4 + tid]);                                \
        const uint4* sa_ = a_src_base + (size_t)(kt) * 256;                           \
        asm volatile("cp.async.cg.shared.global [%0], [%1], 16;\n" :: "r"(da), "l"(sa_)); \
        if (hasB) {                                                                   \
            uint32_t db = (uint32_t)__cvta_generic_to_shared(                         \
                &sm[((kt) & (STG - 1)) * STAGE_U4 + 512 + (tid & 255)]);              \
            const uint4* sb_ = b_src_base + (size_t)(kt) * 256;                       \
            asm volatile("cp.async.cg.shared.global [%0], [%1], 16;\n" :: "r"(db), "l"(sb_)); \
        }                                                                             \
        asm volatile("cp.async.commit_group;\n");                                     \
    }

#define COMPUTE(kt)                                                                   \
    {                                                                                 \
        const int st = (kt) & (STG - 1);                                              \
        uint4 au[4];                                                                  \
        _Pragma("unroll")                                                             \
        for (int mt = 0; mt < 4; ++mt)                                                \
            au[mt] = sm[st * STAGE_U4 + (wm * 4 + mt) * 32 + lane];                   \
        const uint2* b2 = (const uint2*)(sm + st * STAGE_U4 + 512);                   \
        uint2 bu[4];                                                                  \
        _Pragma("unroll")                                                             \
        for (int cg = 0; cg < 4; ++cg)                                                \
            bu[cg] = b2[(wn * 4 + cg) * 32 + lane];                                   \
        _Pragma("unroll")                                                             \
        for (int mt = 0; mt < 4; ++mt)                                                \
            _Pragma("unroll")                                                         \
            for (int cg = 0; cg < 4; ++cg)                                            \
                mma16816(C[mt][cg], au[mt].x, au[mt].y, au[mt].z, au[mt].w,           \
                         bu[cg].x, bu[cg].y);                                         \
    }

#pragma unroll
    for (int kt = 0; kt < STG - 1; ++kt) ISSUE(kt);

#pragma unroll 1
    for (int kt = 0; kt < 64 - (STG - 1); ++kt) {
        asm volatile("cp.async.wait_group %0;\n" :: "n"(STG - 2) : "memory");
        __syncthreads();
        ISSUE(kt + STG - 1);
        COMPUTE(kt);
    }

    asm volatile("cp.async.wait_group 0;\n" ::: "memory");
    __syncthreads();
#pragma unroll
    for (int kt = 64 - (STG - 1); kt < 64; ++kt) {
        COMPUTE(kt);
    }
#undef ISSUE
#undef COMPUTE

    const int g = lane >> 2, tig = lane & 3;
#pragma unroll
    for (int mt = 0; mt < 4; ++mt) {
#pragma unroll
        for (int cg = 0; cg < 4; ++cg) {
            int row = mbBig * 256 + wm * 64 + mt * 16 + g;
            int col = nb * 128 + wn * 32 + cg * 8 + 2 * tig;
            float b0 = bi[col], b1 = bi[col + 1];
            *(float2*)(Y + (size_t)row * G4H + col) =
                make_float2(C[mt][cg][0] + b0, C[mt][cg][1] + b1);
            *(float2*)(Y + (size_t)(row + 8) * G4H + col) =
                make_float2(C[mt][cg][2] + b0, C[mt][cg][3] + b1);
        }
    }
}

// =====================================================================
// Persistent recurrent kernel — R13 math; monotone-counter step barrier;
// xv(t+1) prefetched before the barrier.
// =====================================================================
__global__ void __launch_bounds__(256, 1) recurrent_h(
    const float* __restrict__ xg,   // [T][B][4H]
    const float* __restrict__ R,    // [4H][H]
    const float* __restrict__ bh,   // [4H]
    const float* __restrict__ h0,   // [B][H]
    const float* __restrict__ c0,   // [B][H]
    float* __restrict__ outp,
    float* __restrict__ hT,         // [B][H]
    float* __restrict__ cT,         // [B][H]
    int mode)
{
    __shared__ float part[32 * 296];   // part[b][w][j] : b*296 + w*37 + j

    const int tid  = threadIdx.x;
    const int w    = tid >> 5;
    const int lane = tid & 31;
    const int g    = lane >> 2;
    const int tig  = lane & 3;
    const int n0   = blockIdx.x * 8;

    // Reset monotone step counter (published by the entry barrier below).
    if (blockIdx.x == 0 && tid == 0) g_scnt = 0u;

    // ---- Preload R fp16 B-fragments into registers ----
    uint32_t Br[4][8][2];
#pragma unroll
    for (int cg = 0; cg < 4; ++cg) {
        const float* rp = R + (size_t)(cg * HH + n0 + g) * HH + w * 128 + 2 * tig;
#pragma unroll
        for (int ks = 0; ks < 8; ++ks) {
            const float* q = rp + ks * 16;
            Br[cg][ks][0] = h2pack(__ldg(q),     __ldg(q + 1));
            Br[cg][ks][1] = h2pack(__ldg(q + 8), __ldg(q + 9));
        }
    }

    // ---- Convert h0 into packed fp16 HB[0] (32 slots per block) ----
    if (tid < 32) {
        int slot = blockIdx.x * 32 + tid;            // 0..4095
        int ls = slot & 31, mts = (slot >> 5) & 1, kt = slot >> 6;
        int gs = ls >> 2, ts = ls & 3;
        int r0 = mts * 16 + gs;
        int k0 = kt * 16 + 2 * ts;
        const float* p0 = h0 + (size_t)r0 * HH;
        const float* p1 = h0 + (size_t)(r0 + 8) * HH;
        uint4 v;
        v.x = h2pack(p0[k0],     p0[k0 + 1]);
        v.y = h2pack(p1[k0],     p1[k0 + 1]);
        v.z = h2pack(p0[k0 + 8], p0[k0 + 9]);
        v.w = h2pack(p1[k0 + 8], p1[k0 + 9]);
        g_hb[0][slot] = v;
    }

    // ---- update-phase constants ----
    const int ub = tid >> 3;   // b 0..31
    const int un = tid & 7;    // n-offset 0..7
    const int hid = n0 + un;
    float bhv[4];
#pragma unroll
    for (int gg = 0; gg < 4; ++gg) bhv[gg] = bh[gg * HH + hid];
    float creg = c0[ub * HH + hid];

    // fp16 h write address for (ub, hid) inside HB slot
    const int hw_mt = ub >> 4, hw_row16 = ub & 15;
    const int hw_g = hw_row16 & 7, hw_rh = hw_row16 >> 3;
    const int hw_kt = hid >> 4, hw_k15 = hid & 15;
    const int hw_kh = hw_k15 >> 3, hw_tig = (hw_k15 & 7) >> 1, hw_hs = hw_k15 & 1;
    const int hb_slot = (hw_kt * 2 + hw_mt) * 32 + hw_g * 4 + hw_tig;
    const int hb_half = (hw_kh * 2 + hw_rh) * 2 + hw_hs;   // half index within uint4
    __half* hb_w[2] = { (__half*)&g_hb[0][hb_slot] + hb_half,
                        (__half*)&g_hb[1][hb_slot] + hb_half };

    // Prefetch xv for t=0 (xg is ready: producer kernel is stream-ordered).
    float xv[4];
    {
        const float* xgt = xg + (size_t)ub * G4H + hid;
#pragma unroll
        for (int gg = 0; gg < 4; ++gg) xv[gg] = __ldg(xgt + gg * HH);
    }

    grid_barrier_atomic();   // HB[0] + g_scnt reset visible everywhere

    for (int t = 0; t < TT; ++t) {
        const uint4* hp = g_hb[t & 1];

        // Burst-prefetch ALL 16 h fragments (MLP=16, one L2 latency exposure)
        uint4 Ab[8][2];
#pragma unroll
        for (int p = 0; p < 8; ++p)
#pragma unroll
            for (int mt = 0; mt < 2; ++mt)
                Ab[p][mt] = __ldcg(&hp[((w * 8 + p) * 2 + mt) * 32 + lane]);

        float Cr[2][4][4];
#pragma unroll
        for (int a = 0; a < 2; ++a)
#pragma unroll
            for (int b = 0; b < 4; ++b)
#pragma unroll
                for (int c = 0; c < 4; ++c) Cr[a][b][c] = 0.0f;

#pragma unroll
        for (int ks = 0; ks < 8; ++ks) {
            uint4 a0 = Ab[ks][0];
            uint4 a1 = Ab[ks][1];
#pragma unroll
            for (int cg = 0; cg < 4; ++cg) {
                mma16816(Cr[0][cg], a0.x, a0.y, a0.z, a0.w, Br[cg][ks][0], Br[cg][ks][1]);
                mma16816(Cr[1][cg], a1.x, a1.y, a1.z, a1.w, Br[cg][ks][0], Br[cg][ks][1]);
            }
        }

        // store partials to smem (SCALAR stores: stride 37 is odd -> no float2)
#pragma unroll
        for (int mt = 0; mt < 2; ++mt) {
#pragma unroll
            for (int cg = 0; cg < 4; ++cg) {
                int b = mt * 16 + g;
                int jj = cg * 8 + 2 * tig;
                part[b * 296 + w * 37 + jj]           = Cr[mt][cg][0];
                part[b * 296 + w * 37 + jj + 1]       = Cr[mt][cg][1];
                part[(b + 8) * 296 + w * 37 + jj]     = Cr[mt][cg][2];
                part[(b + 8) * 296 + w * 37 + jj + 1] = Cr[mt][cg][3];
            }
        }
        __syncthreads();

        // reduce over 8 warps + gate math. gates order: i, o, z, f
        float gate[4];
#pragma unroll
        for (int gg = 0; gg < 4; ++gg) {
            float s = xv[gg] + bhv[gg];
#pragma unroll
            for (int wi = 0; wi < 8; ++wi)
                s += part[ub * 296 + wi * 37 + gg * 8 + un];
            gate[gg] = sigm(s);
        }
        creg = creg * gate[3] + gate[2] - gate[0];   // c = c*f + z - i
        float hval = sigm(creg) - gate[1];           // h = sigm(c) - o

        if (mode == 0) {
            // packed-A fp16 layout for layer-1 gemm
            int m = t * BB + ub;
            int mb = m >> 7, r = m & 127;
            int rg_ = r >> 4, row16 = r & 15;
            int g_ = row16 & 7, rh_ = row16 >> 3;
            size_t slot = ((size_t)(mb * 64 + hw_kt) * 8 + rg_) * 32 + g_ * 4 + hw_tig;
            ((__half*)&((uint4*)outp)[slot])[(hw_kh * 2 + rh_) * 2 + hw_hs] =
                __float2half_rn(hval);
        } else {
            outp[((size_t)t * BB + ub) * HH + hid] = hval;
        }

        // fp16 HB store for next step
        *hb_w[(t + 1) & 1] = __float2half_rn(hval);

        if (t == TT - 1) {
            hT[ub * HH + hid] = hval;
            cT[ub * HH + hid] = creg;
        } else {
            // Prefetch xv for t+1 BEFORE the barrier (latency hidden by wait)
            const float* xgt = xg + ((size_t)(t + 1) * BB + ub) * G4H + hid;
#pragma unroll
            for (int gg = 0; gg < 4; ++gg) xv[gg] = __ldg(xgt + gg * HH);
            step_barrier(t);
        }
    }
}

// ---------------- launch ----------------
extern "C" void kernel_launch(void* const* d_in, const int* in_sizes, int n_in,
                              void* d_out, int out_size)
{
    (void)in_sizes; (void)n_in; (void)out_size;
    const float* x   = (const float*)d_in[0];
    const float* h0  = (const float*)d_in[1];
    const float* c0  = (const float*)d_in[2];
    const float* W0  = (const float*)d_in[3];
    const float* R0  = (const float*)d_in[4];
    const float* bi0 = (const float*)d_in[5];
    const float* bh0 = (const float*)d_in[6];
    const float* W1  = (const float*)d_in[7];
    const float* R1  = (const float*)d_in[8];
    const float* bi1 = (const float*)d_in[9];
    const float* bh1 = (const float*)d_in[10];

    float* out = (float*)d_out;
    float* hT  = out + (size_t)TT * BB * HH;
    float* cT  = hT + (size_t)2 * BB * HH;

    float* xg = nullptr;  cudaGetSymbolAddress((void**)&xg, g_xg);
    uint4* xa = nullptr;  cudaGetSymbolAddress((void**)&xa, g_xa);
    uint4* x1 = nullptr;  cudaGetSymbolAddress((void**)&x1, g_x1);
    uint4* wb = nullptr;  cudaGetSymbolAddress((void**)&wb, g_wb);

    cudaFuncSetAttribute(gemm_h, cudaFuncAttributeMaxDynamicSharedMemorySize, GEMM_SMEM);

    dim3 ggrid(G4H / 128, (TT * BB) / 256);  // (32, 64)

    // Layer 0
    conv_pack_a<<<2097152 / 256, 256>>>(x, xa);
    conv_pack_b<<<1048576 / 256, 256>>>(W0, (uint2*)wb);
    gemm_h<<<ggrid, 512, GEMM_SMEM>>>(xa, wb, bi0, xg);
    recurrent_h<<<NBLK, 256>>>(xg, R0, bh0, h0, c0, (float*)x1, hT, cT, 0);
    // Layer 1
    conv_pack_b<<<1048576 / 256, 256>>>(W1, (uint2*)wb);
    gemm_h<<<ggrid, 512, GEMM_SMEM>>>(x1, wb, bi1, xg);
    recurrent_h<<<NBLK, 256>>>(xg, R1, bh1, h0 + BB * HH, c0 + BB * HH,
                               out, hT + BB * HH, cT + BB * HH, 1);
}

// round 17
// speedup vs baseline: 1.3913x; 1.0960x over previous
#include <cuda_runtime.h>
#include <cuda_fp16.h>
#include <cstdint>
#include <cstddef>

// Problem constants
#define TT   512
#define BB   32
#define HH   1024
#define G4H  4096
#define NBLK 128           // persistent recurrent grid (co-resident)

// ---------------- scratch ----------------
__device__ float g_xg[(size_t)TT * BB * G4H];     // input projection (fp32 [t][b][4H])
__device__ uint4 g_xa[2097152];                   // packed-A fp16 X (layer 0), 32MB
__device__ uint4 g_x1[2097152];                   // packed-A fp16 layer-0 output, 32MB
__device__ uint4 g_wb[1048576];                   // packed-B fp16 weights (16MB), per layer
__device__ uint4 g_hb[2][4096];                   // packed-A fp16 hidden state, ping-pong (2x64KB)
__device__ unsigned int          g_cnt;           // entry barrier counter
__device__ volatile unsigned int g_gen;           // entry barrier generation
__device__ unsigned int          g_scnt;          // monotone step counter (reset at entry)

__device__ __forceinline__ float sigm(float x) {
    return 1.0f / (1.0f + expf(-x));
}

// pack two floats into one fp16x2 register (lo = first arg)
__device__ __forceinline__ uint32_t h2pack(float lo, float hi) {
    __half2 h = __floats2half2_rn(lo, hi);
    return *(uint32_t*)&h;
}

// fp16 tensor-core mma, fp32 accumulate
__device__ __forceinline__ void mma16816(float c[4],
    uint32_t a0, uint32_t a1, uint32_t a2, uint32_t a3,
    uint32_t b0, uint32_t b1)
{
    asm volatile(
        "mma.sync.aligned.m16n8k16.row.col.f32.f16.f16.f32 "
        "{%0,%1,%2,%3}, {%4,%5,%6,%7}, {%8,%9}, {%0,%1,%2,%3};"
        : "+f"(c[0]), "+f"(c[1]), "+f"(c[2]), "+f"(c[3])
        : "r"(a0), "r"(a1), "r"(a2), "r"(a3), "r"(b0), "r"(b1));
}

// Release-RED arrival: single instruction, orders prior writes (no MEMBAR).
__device__ __forceinline__ void red_release_add(unsigned int* p) {
    asm volatile("red.release.gpu.global.add.u32 [%0], %1;"
                 :: "l"(p), "r"(1u) : "memory");
}
// Acquire poll load (replaces volatile load + trailing threadfence).
__device__ __forceinline__ unsigned int ld_acquire(unsigned int* p) {
    unsigned int v;
    asm volatile("ld.acquire.gpu.global.u32 %0, [%1];"
                 : "=r"(v) : "l"(p) : "memory");
    return v;
}

// Atomic entry barrier (R1-R16 proven pattern). Used once per launch:
// publishes HB[0], R preload visibility, and the g_scnt reset.
__device__ __forceinline__ void grid_barrier_atomic() {
    __syncthreads();
    if (threadIdx.x == 0) {
        __threadfence();
        unsigned int g = g_gen;
        if (atomicAdd(&g_cnt, 1u) == NBLK - 1u) {
            g_cnt = 0u;
            __threadfence();
            g_gen = g + 1u;
        } else {
            while (g_gen == g) { }
        }
        __threadfence();
    }
    __syncthreads();
}

// =====================================================================
// Packing converters (fp32 -> fp16 mma fragments)
// =====================================================================
__global__ void __launch_bounds__(256) conv_pack_a(
    const float* __restrict__ X, uint4* __restrict__ Ap)
{
    int s = blockIdx.x * 256 + threadIdx.x;
    int lane = s & 31, rg = (s >> 5) & 7, kt = (s >> 8) & 63, mb = s >> 14;
    int g = lane >> 2, tig = lane & 3;
    int r0 = mb * 128 + rg * 16 + g;
    int k0 = kt * 16 + 2 * tig;
    const float* p0 = X + (size_t)r0 * HH;
    const float* p1 = X + (size_t)(r0 + 8) * HH;
    uint4 v;
    v.x = h2pack(p0[k0],     p0[k0 + 1]);
    v.y = h2pack(p1[k0],     p1[k0 + 1]);
    v.z = h2pack(p0[k0 + 8], p0[k0 + 9]);
    v.w = h2pack(p1[k0 + 8], p1[k0 + 9]);
    Ap[s] = v;
}

__global__ void __launch_bounds__(256) conv_pack_b(
    const float* __restrict__ W, uint2* __restrict__ Bp)
{
    int s = blockIdx.x * 256 + threadIdx.x;
    int lane = s & 31, cg = (s >> 5) & 15, kt = (s >> 9) & 63, nb = s >> 15;
    int g = lane >> 2, tig = lane & 3;
    int n  = nb * 128 + cg * 8 + g;
    int k0 = kt * 16 + 2 * tig;
    const float* p = W + (size_t)n * HH;
    Bp[s] = make_uint2(h2pack(p[k0], p[k0 + 1]), h2pack(p[k0 + 8], p[k0 + 9]));
}

// =====================================================================
// Input projection GEMM, 256x128 tile, fp16 tensor cores,
// cp.async 8-deep smem pipeline with proper tail drain. (R13, unchanged.)
// =====================================================================
#define STG 8
#define STAGE_U4 768
#define GEMM_SMEM (STG * STAGE_U4 * 16)   // 98304 bytes

__global__ void __launch_bounds__(512, 1) gemm_h(
    const uint4* __restrict__ Ap, const uint4* __restrict__ Bp4,
    const float* __restrict__ bi, float* __restrict__ Y)
{
    extern __shared__ uint4 sm[];   // [stage*768 + (A:0..511 | B:512..767)]

    const int tid  = threadIdx.x;
    const int warp = tid >> 5;
    const int lane = tid & 31;
    const int wm   = warp >> 2;      // 0..3 (m, 64 rows each)
    const int wn   = warp & 3;       // 0..3 (n, 32 cols each)
    const int nb   = blockIdx.x;
    const int mbBig = blockIdx.y;    // 256-row block

    const int a_rgBig = (tid >> 5) & 15;
    const int a_mb128 = 2 * mbBig + (a_rgBig >> 3);
    const uint4* a_src_base = Ap + (size_t)a_mb128 * 16384 + ((size_t)(a_rgBig & 7)) * 32 + lane;
    const uint4* b_src_base = Bp4 + (size_t)nb * 16384 + (tid & 255);
    const bool hasB = tid < 256;

    float C[4][4][4];
#pragma unroll
    for (int a = 0; a < 4; ++a)
#pragma unroll
        for (int b = 0; b < 4; ++b)
#pragma unroll
            for (int c = 0; c < 4; ++c) C[a][b][c] = 0.0f;

#define ISSUE(kt)                                                                     \
    {                                                                                 \
        uint32_t da = (uint32_t)__cvta_generic_to_shared(                             \
            &sm[((kt) & (STG - 1)) * STAGE_U4 + tid]);                                \
        const uint4* sa_ = a_src_base + (size_t)(kt) * 256;                           \
        asm volatile("cp.async.cg.shared.global [%0], [%1], 16;\n" :: "r"(da), "l"(sa_)); \
        if (hasB) {                                                                   \
            uint32_t db = (uint32_t)__cvta_generic_to_shared(                         \
                &sm[((kt) & (STG - 1)) * STAGE_U4 + 512 + (tid & 255)]);              \
            const uint4* sb_ = b_src_base + (size_t)(kt) * 256;                       \
            asm volatile("cp.async.cg.shared.global [%0], [%1], 16;\n" :: "r"(db), "l"(sb_)); \
        }                                                                             \
        asm volatile("cp.async.commit_group;\n");                                     \
    }

#define COMPUTE(kt)                                                                   \
    {                                                                                 \
        const int st = (kt) & (STG - 1);                                              \
        uint4 au[4];                                                                  \
        _Pragma("unroll")                                                             \
        for (int mt = 0; mt < 4; ++mt)                                                \
            au[mt] = sm[st * STAGE_U4 + (wm * 4 + mt) * 32 + lane];                   \
        const uint2* b2 = (const uint2*)(sm + st * STAGE_U4 + 512);                   \
        uint2 bu[4];                                                                  \
        _Pragma("unroll")                                                             \
        for (int cg = 0; cg < 4; ++cg)                                                \
            bu[cg] = b2[(wn * 4 + cg) * 32 + lane];                                   \
        _Pragma("unroll")                                                             \
        for (int mt = 0; mt < 4; ++mt)                                                \
            _Pragma("unroll")                                                         \
            for (int cg = 0; cg < 4; ++cg)                                            \
                mma16816(C[mt][cg], au[mt].x, au[mt].y, au[mt].z, au[mt].w,           \
                         bu[cg].x, bu[cg].y);                                         \
    }

#pragma unroll
    for (int kt = 0; kt < STG - 1; ++kt) ISSUE(kt);

#pragma unroll 1
    for (int kt = 0; kt < 64 - (STG - 1); ++kt) {
        asm volatile("cp.async.wait_group %0;\n" :: "n"(STG - 2) : "memory");
        __syncthreads();
        ISSUE(kt + STG - 1);
        COMPUTE(kt);
    }

    asm volatile("cp.async.wait_group 0;\n" ::: "memory");
    __syncthreads();
#pragma unroll
    for (int kt = 64 - (STG - 1); kt < 64; ++kt) {
        COMPUTE(kt);
    }
#undef ISSUE
#undef COMPUTE

    const int g = lane >> 2, tig = lane & 3;
#pragma unroll
    for (int mt = 0; mt < 4; ++mt) {
#pragma unroll
        for (int cg = 0; cg < 4; ++cg) {
            int row = mbBig * 256 + wm * 64 + mt * 16 + g;
            int col = nb * 128 + wn * 32 + cg * 8 + 2 * tig;
            float b0 = bi[col], b1 = bi[col + 1];
            *(float2*)(Y + (size_t)row * G4H + col) =
                make_float2(C[mt][cg][0] + b0, C[mt][cg][1] + b1);
            *(float2*)(Y + (size_t)(row + 8) * G4H + col) =
                make_float2(C[mt][cg][2] + b0, C[mt][cg][3] + b1);
        }
    }
}

// =====================================================================
// Persistent recurrent kernel — R16 math; release/acquire step barrier;
// outp store + xv prefetch hidden under the barrier poll.
// =====================================================================
__global__ void __launch_bounds__(256, 1) recurrent_h(
    const float* __restrict__ xg,   // [T][B][4H]
    const float* __restrict__ R,    // [4H][H]
    const float* __restrict__ bh,   // [4H]
    const float* __restrict__ h0,   // [B][H]
    const float* __restrict__ c0,   // [B][H]
    float* __restrict__ outp,
    float* __restrict__ hT,         // [B][H]
    float* __restrict__ cT,         // [B][H]
    int mode)
{
    __shared__ float part[32 * 296];   // part[b][w][j] : b*296 + w*37 + j

    const int tid  = threadIdx.x;
    const int w    = tid >> 5;
    const int lane = tid & 31;
    const int g    = lane >> 2;
    const int tig  = lane & 3;
    const int n0   = blockIdx.x * 8;

    // Reset monotone step counter (published by the entry barrier below).
    if (blockIdx.x == 0 && tid == 0) g_scnt = 0u;

    // ---- Preload R fp16 B-fragments into registers ----
    uint32_t Br[4][8][2];
#pragma unroll
    for (int cg = 0; cg < 4; ++cg) {
        const float* rp = R + (size_t)(cg * HH + n0 + g) * HH + w * 128 + 2 * tig;
#pragma unroll
        for (int ks = 0; ks < 8; ++ks) {
            const float* q = rp + ks * 16;
            Br[cg][ks][0] = h2pack(__ldg(q),     __ldg(q + 1));
            Br[cg][ks][1] = h2pack(__ldg(q + 8), __ldg(q + 9));
        }
    }

    // ---- Convert h0 into packed fp16 HB[0] (32 slots per block) ----
    if (tid < 32) {
        int slot = blockIdx.x * 32 + tid;            // 0..4095
        int ls = slot & 31, mts = (slot >> 5) & 1, kt = slot >> 6;
        int gs = ls >> 2, ts = ls & 3;
        int r0 = mts * 16 + gs;
        int k0 = kt * 16 + 2 * ts;
        const float* p0 = h0 + (size_t)r0 * HH;
        const float* p1 = h0 + (size_t)(r0 + 8) * HH;
        uint4 v;
        v.x = h2pack(p0[k0],     p0[k0 + 1]);
        v.y = h2pack(p1[k0],     p1[k0 + 1]);
        v.z = h2pack(p0[k0 + 8], p0[k0 + 9]);
        v.w = h2pack(p1[k0 + 8], p1[k0 + 9]);
        g_hb[0][slot] = v;
    }

    // ---- update-phase constants ----
    const int ub = tid >> 3;   // b 0..31
    const int un = tid & 7;    // n-offset 0..7
    const int hid = n0 + un;
    float bhv[4];
#pragma unroll
    for (int gg = 0; gg < 4; ++gg) bhv[gg] = bh[gg * HH + hid];
    float creg = c0[ub * HH + hid];

    // fp16 h write address for (ub, hid) inside HB slot
    const int hw_mt = ub >> 4, hw_row16 = ub & 15;
    const int hw_g = hw_row16 & 7, hw_rh = hw_row16 >> 3;
    const int hw_kt = hid >> 4, hw_k15 = hid & 15;
    const int hw_kh = hw_k15 >> 3, hw_tig = (hw_k15 & 7) >> 1, hw_hs = hw_k15 & 1;
    const int hb_slot = (hw_kt * 2 + hw_mt) * 32 + hw_g * 4 + hw_tig;
    const int hb_half = (hw_kh * 2 + hw_rh) * 2 + hw_hs;   // half index within uint4
    __half* hb_w[2] = { (__half*)&g_hb[0][hb_slot] + hb_half,
                        (__half*)&g_hb[1][hb_slot] + hb_half };

    // Prefetch xv for t=0 (xg is ready: producer kernel is stream-ordered).
    float xv[4];
    {
        const float* xgt = xg + (size_t)ub * G4H + hid;
#pragma unroll
        for (int gg = 0; gg < 4; ++gg) xv[gg] = __ldg(xgt + gg * HH);
    }

    grid_barrier_atomic();   // HB[0] + g_scnt reset visible everywhere

    for (int t = 0; t < TT; ++t) {
        const uint4* hp = g_hb[t & 1];

        // Burst-prefetch ALL 16 h fragments (MLP=16, one L2 latency exposure)
        uint4 Ab[8][2];
#pragma unroll
        for (int p = 0; p < 8; ++p)
#pragma unroll
            for (int mt = 0; mt < 2; ++mt)
                Ab[p][mt] = __ldcg(&hp[((w * 8 + p) * 2 + mt) * 32 + lane]);

        float Cr[2][4][4];
#pragma unroll
        for (int a = 0; a < 2; ++a)
#pragma unroll
            for (int b = 0; b < 4; ++b)
#pragma unroll
                for (int c = 0; c < 4; ++c) Cr[a][b][c] = 0.0f;

#pragma unroll
        for (int ks = 0; ks < 8; ++ks) {
            uint4 a0 = Ab[ks][0];
            uint4 a1 = Ab[ks][1];
#pragma unroll
            for (int cg = 0; cg < 4; ++cg) {
                mma16816(Cr[0][cg], a0.x, a0.y, a0.z, a0.w, Br[cg][ks][0], Br[cg][ks][1]);
                mma16816(Cr[1][cg], a1.x, a1.y, a1.z, a1.w, Br[cg][ks][0], Br[cg][ks][1]);
            }
        }

        // store partials to smem (SCALAR stores: stride 37 is odd -> no float2)
#pragma unroll
        for (int mt = 0; mt < 2; ++mt) {
#pragma unroll
            for (int cg = 0; cg < 4; ++cg) {
                int b = mt * 16 + g;
                int jj = cg * 8 + 2 * tig;
                part[b * 296 + w * 37 + jj]           = Cr[mt][cg][0];
                part[b * 296 + w * 37 + jj + 1]       = Cr[mt][cg][1];
                part[(b + 8) * 296 + w * 37 + jj]     = Cr[mt][cg][2];
                part[(b + 8) * 296 + w * 37 + jj + 1] = Cr[mt][cg][3];
            }
        }
        __syncthreads();

        // reduce over 8 warps + gate math. gates order: i, o, z, f
        float gate[4];
#pragma unroll
        for (int gg = 0; gg < 4; ++gg) {
            float s = xv[gg] + bhv[gg];
#pragma unroll
            for (int wi = 0; wi < 8; ++wi)
                s += part[ub * 296 + wi * 37 + gg * 8 + un];
            gate[gg] = sigm(s);
        }
        creg = creg * gate[3] + gate[2] - gate[0];   // c = c*f + z - i
        float hval = sigm(creg) - gate[1];           // h = sigm(c) - o

        // Cross-block-visible store FIRST (the only one the barrier must cover)
        *hb_w[(t + 1) & 1] = __float2half_rn(hval);

        if (t == TT - 1) {
            // Final step: no barrier; kernel-end implies visibility.
            if (mode == 0) {
                int m = t * BB + ub;
                int mb = m >> 7, r = m & 127;
                int rg_ = r >> 4, row16 = r & 15;
                int g_ = row16 & 7, rh_ = row16 >> 3;
                size_t slot = ((size_t)(mb * 64 + hw_kt) * 8 + rg_) * 32 + g_ * 4 + hw_tig;
                ((__half*)&((uint4*)outp)[slot])[(hw_kh * 2 + rh_) * 2 + hw_hs] =
                    __float2half_rn(hval);
            } else {
                outp[((size_t)t * BB + ub) * HH + hid] = hval;
            }
            hT[ub * HH + hid] = hval;
            cT[ub * HH + hid] = creg;
        } else {
            __syncthreads();   // all threads' h stores issued
            if (tid == 0) red_release_add(&g_scnt);   // single-instr release arrival

            // ---- hidden under the barrier poll: outp store + xv prefetch ----
            if (mode == 0) {
                int m = t * BB + ub;
                int mb = m >> 7, r = m & 127;
                int rg_ = r >> 4, row16 = r & 15;
                int g_ = row16 & 7, rh_ = row16 >> 3;
                size_t slot = ((size_t)(mb * 64 + hw_kt) * 8 + rg_) * 32 + g_ * 4 + hw_tig;
                ((__half*)&((uint4*)outp)[slot])[(hw_kh * 2 + rh_) * 2 + hw_hs] =
                    __float2half_rn(hval);
            } else {
                outp[((size_t)t * BB + ub) * HH + hid] = hval;
            }
            {
                const float* xgt = xg + ((size_t)(t + 1) * BB + ub) * G4H + hid;
#pragma unroll
                for (int gg = 0; gg < 4; ++gg) xv[gg] = __ldg(xgt + gg * HH);
            }

            if (tid == 0) {
                const unsigned int tgt = (unsigned int)(NBLK * (t + 1));
                while (ld_acquire(&g_scnt) < tgt) { }
            }
            __syncthreads();
        }
    }
}

// ---------------- launch ----------------
extern "C" void kernel_launch(void* const* d_in, const int* in_sizes, int n_in,
                              void* d_out, int out_size)
{
    (void)in_sizes; (void)n_in; (void)out_size;
    const float* x   = (const float*)d_in[0];
    const float* h0  = (const float*)d_in[1];
    const float* c0  = (const float*)d_in[2];
    const float* W0  = (const float*)d_in[3];
    const float* R0  = (const float*)d_in[4];
    const float* bi0 = (const float*)d_in[5];
    const float* bh0 = (const float*)d_in[6];
    const float* W1  = (const float*)d_in[7];
    const float* R1  = (const float*)d_in[8];
    const float* bi1 = (const float*)d_in[9];
    const float* bh1 = (const float*)d_in[10];

    float* out = (float*)d_out;
    float* hT  = out + (size_t)TT * BB * HH;
    float* cT  = hT + (size_t)2 * BB * HH;

    float* xg = nullptr;  cudaGetSymbolAddress((void**)&xg, g_xg);
    uint4* xa = nullptr;  cudaGetSymbolAddress((void**)&xa, g_xa);
    uint4* x1 = nullptr;  cudaGetSymbolAddress((void**)&x1, g_x1);
    uint4* wb = nullptr;  cudaGetSymbolAddress((void**)&wb, g_wb);

    cudaFuncSetAttribute(gemm_h, cudaFuncAttributeMaxDynamicSharedMemorySize, GEMM_SMEM);

    dim3 ggrid(G4H / 128, (TT * BB) / 256);  // (32, 64)

    // Layer 0
    conv_pack_a<<<2097152 / 256, 256>>>(x, xa);
    conv_pack_b<<<1048576 / 256, 256>>>(W0, (uint2*)wb);
    gemm_h<<<ggrid, 512, GEMM_SMEM>>>(xa, wb, bi0, xg);
    recurrent_h<<<NBLK, 256>>>(xg, R0, bh0, h0, c0, (float*)x1, hT, cT, 0);
    // Layer 1
    conv_pack_b<<<1048576 / 256, 256>>>(W1, (uint2*)wb);
    gemm_h<<<ggrid, 512, GEMM_SMEM>>>(x1, wb, bi1, xg);
    recurrent_h<<<NBLK, 256>>>(xg, R1, bh1, h0 + BB * HH, c0 + BB * HH,
                               out, hT + BB * HH, cT + BB * HH, 1);
}